// round 16
// baseline (speedup 1.0000x reference)
#include <cuda_runtime.h>
#include <cuda_bf16.h>

// ZBL basis: per-edge screened Coulomb repulsion with polynomial cutoff,
// scatter-summed into receiver nodes.
//
// Inputs (metadata order):
//   d_in[0]: x               float32 [E, 1]   (E = 3,200,000)
//   d_in[1]: node_attrs      float32 [N, 10]  (N = 100,000)
//   d_in[2]: edge_index      int32   [2, E]
//   d_in[3]: atomic_numbers  int32   [10]
//   d_in[4]: covalent_radii  float32 [119]
// Output: V_ZBL float32 [N]
//
// Converged configuration + one new lever:
//  - edge: nibble element table (50KB smem) + 8x-replicated float4 pair LUT
//    (12.8KB, conflict-free LDS.128) + software-pipelined streaming loads +
//    predicated red.global.add; (512 thr, 2 blocks)/SM, grid 296, one wave.
//  - NEW: all read-once streaming loads use ld.global.cg (__ldcg): no L1
//    allocation -> no L1 fill traffic for 38.4MB of streams, freeing L1TEX
//    tag/data bandwidth for the gathers + REDs that sit on the kernel's
//    measured wavefront floor.
//  - node_prep: register-resident argmax, 2 nodes/thread, fused zeroing.

#define MAX_NODES 100352            // >= N, even, multiple of 32
#define PACKED_N  (MAX_NODES / 2)   // nibble-packed element table bytes
#define N_ELEMS   10
#define NPAIR     (N_ELEMS * N_ELEMS)
#define NT        512
#define EDGE_GRID 296               // 2 blocks/SM x 148 SMs, one wave
#define NP_NT     128               // node_prep block size

__device__ unsigned char g_e4[PACKED_N];   // 2 nodes/byte: elem idx nibbles

__device__ __forceinline__ float ex2f(float a) {
    float r; asm("ex2.approx.f32 %0, %1;" : "=f"(r) : "f"(a)); return r;
}
__device__ __forceinline__ float frcpf(float a) {
    float r; asm("rcp.approx.f32 %0, %1;" : "=f"(r) : "f"(a)); return r;
}

// Predicated no-return global float add; no memory clobber (write-only out).
__device__ __forceinline__ void red_add_if(float* addr, float val, float rr) {
    asm volatile(
        "{\n\t"
        ".reg .pred p;\n\t"
        "setp.lt.f32 p, %1, 0f3F800000;\n\t"   // rr < 1.0f
        "@p red.global.add.f32 [%0], %2;\n\t"
        "}"
        :: "l"(addr), "f"(rr), "f"(val));
}

// ---------------------------------------------------------------------------
// Node prep: 2 adjacent nodes per thread, all in registers.
// ---------------------------------------------------------------------------
__device__ __forceinline__ int argmax10(const float* v) {
    int best = 0;
    float bv = v[0];
#pragma unroll
    for (int j = 1; j < N_ELEMS; j++) {
        if (v[j] > bv) { bv = v[j]; best = j; }
    }
    return best;
}

__global__ void __launch_bounds__(NP_NT)
node_prep_kernel(const float* __restrict__ attrs,
                 float* __restrict__ out,
                 int n_nodes, int out_n) {
    int t = blockIdx.x * NP_NT + threadIdx.x;  // thread owns nodes 2t, 2t+1
    int n0 = 2 * t;

    if (n0 < n_nodes) {
        float v[20];
        const float4* a4 = (const float4*)(attrs + (size_t)n0 * N_ELEMS);
        // 5 independent float4 loads: 80 bytes = 2 nodes x 10 attrs
#pragma unroll
        for (int k = 0; k < 5; k++) {
            float4 q = __ldcg(a4 + k);
            v[4 * k + 0] = q.x; v[4 * k + 1] = q.y;
            v[4 * k + 2] = q.z; v[4 * k + 3] = q.w;
        }
        unsigned char packed = (unsigned char)argmax10(v);
        if (n0 + 1 < n_nodes)
            packed |= (unsigned char)(argmax10(v + N_ELEMS) << 4);
        g_e4[t] = packed;
    }

    // zero outputs: 2 per thread
    if (n0 < out_n)     out[n0] = 0.0f;
    if (n0 + 1 < out_n) out[n0 + 1] = 0.0f;
}

// ---------------------------------------------------------------------------
// Edge kernel
// ---------------------------------------------------------------------------
__device__ __forceinline__ void process_edge(
    int s, int r, float xi, int lane8,
    const unsigned char* __restrict__ s_e4,
    const float4* __restrict__ s_lut,   // [(eu*10+ev)*8 + (lane&7)]
    float* __restrict__ out)
{
    int eu = (s_e4[s >> 1] >> ((s & 1) << 2)) & 15;
    int ev = (s_e4[r >> 1] >> ((r & 1) << 2)) & 15;
    float4 p = s_lut[((eu * N_ELEMS + ev) << 3) + lane8];
    // p = (inv_rmax, invA, pref, 0)

    float rr = xi * p.x;
    float t  = xi * p.y;

    const float K0 = -3.2f    * 1.44269504f;
    const float K1 = -0.9423f * 1.44269504f;
    const float K2 = -0.4028f * 1.44269504f;
    const float K3 = -0.2016f * 1.44269504f;
    float phi = 0.1818f  * ex2f(K0 * t)
              + 0.5099f  * ex2f(K1 * t)
              + 0.2802f  * ex2f(K2 * t)
              + 0.02817f * ex2f(K3 * t);

    // polynomial envelope, p=6: 1 - 28 r^6 + 48 r^7 - 21 r^8
    float r2 = rr * rr;
    float r3 = r2 * rr;
    float r6 = r3 * r3;
    float env = fmaf(-28.0f, r6, 1.0f);
    env = fmaf(48.0f, r6 * rr, env);
    env = fmaf(-21.0f, r6 * r2, env);

    float val = p.z * phi * frcpf(xi) * env;
    red_add_if(out + r, val, rr);
}

__global__ void __launch_bounds__(NT, 2)
edge_kernel(const float* __restrict__ x,
            const int* __restrict__ ei,
            const int* __restrict__ atomic_numbers,
            const float* __restrict__ radii_g,
            float* __restrict__ out,
            int n_edges, int n_nodes) {
    extern __shared__ char smem[];
    float4* s_lut = (float4*)smem;                  // NPAIR*8 float4 = 12.8KB
    unsigned char* s_e4 = (unsigned char*)(s_lut + NPAIR * 8);

    int tid = threadIdx.x;
    int lane8 = tid & 7;

    // 8x-replicated float4 pair LUT (entry e copy c at [e*8+c]): every
    // 8-lane LDS.128 phase spans all 32 banks -> conflict-free.
    if (tid < NPAIR) {
        int i = tid / N_ELEMS, j = tid % N_ELEMS;
        int Zi = atomic_numbers[i], Zj = atomic_numbers[j];
        float Zif = (float)Zi, Zjf = (float)Zj;
        float irm = 1.0f / (radii_g[Zi] + radii_g[Zj]);
        float ia  = (powf(Zif, 0.3f) + powf(Zjf, 0.3f))
                    * (1.0f / (0.4543f * 0.529f));
        float pf  = 0.5f * 14.3996f * Zif * Zjf;
        float4 v = make_float4(irm, ia, pf, 0.0f);
        int b = tid << 3;
#pragma unroll
        for (int c = 0; c < 8; c++) s_lut[b + c] = v;
    }
    // Copy packed nibble table into smem (16B-wide, coalesced, read-once
    // from L2 -> .cg, no L1 allocation)
    {
        const uint4* ge = (const uint4*)g_e4;
        uint4* se = (uint4*)s_e4;
        int nvec = (((n_nodes + 1) >> 1) + 15) >> 4;
        for (int w = tid; w < nvec; w += NT) se[w] = __ldcg(ge + w);
    }
    __syncthreads();

    const int4*   si = (const int4*)ei;
    const int4*   ri = (const int4*)(ei + n_edges);
    const float4* x4 = (const float4*)x;
    int n4 = n_edges >> 2;

    // Block-balanced contiguous chunk; threads stride NT within it.
    int q   = n4 / gridDim.x;
    int rem = n4 - q * gridDim.x;
    int b   = blockIdx.x;
    int start = b * q + (b < rem ? b : rem);
    int end   = start + q + (b < rem ? 1 : 0);

    int g = start + tid;
    // Software pipeline: hold current iteration's data in registers, issue
    // next iteration's loads before processing (hides streaming-LDG latency).
    // All streams are read-once: .cg keeps them out of L1.
    int4 ss, rr; float4 xx;
    bool act = g < end;
    if (act) { ss = __ldcg(si + g); rr = __ldcg(ri + g); xx = __ldcg(x4 + g); }

    while (act) {
        int gn = g + NT;
        bool actn = gn < end;
        int4 ssn, rrn; float4 xxn;
        if (actn) {
            ssn = __ldcg(si + gn); rrn = __ldcg(ri + gn); xxn = __ldcg(x4 + gn);
        }

        process_edge(ss.x, rr.x, xx.x, lane8, s_e4, s_lut, out);
        process_edge(ss.y, rr.y, xx.y, lane8, s_e4, s_lut, out);
        process_edge(ss.z, rr.z, xx.z, lane8, s_e4, s_lut, out);
        process_edge(ss.w, rr.w, xx.w, lane8, s_e4, s_lut, out);

        ss = ssn; rr = rrn; xx = xxn;
        g = gn; act = actn;
    }

    // scalar tail (n_edges not divisible by 4)
    for (int i = (n4 << 2) + blockIdx.x * NT + tid; i < n_edges;
         i += gridDim.x * NT) {
        process_edge(__ldcg(ei + i), __ldcg(ei + n_edges + i), __ldcg(x + i),
                     lane8, s_e4, s_lut, out);
    }
}

extern "C" void kernel_launch(void* const* d_in, const int* in_sizes, int n_in,
                              void* d_out, int out_size) {
    const float* x              = (const float*)d_in[0];
    const float* node_attrs     = (const float*)d_in[1];
    const int*   edge_index     = (const int*)  d_in[2];
    const int*   atomic_numbers = (const int*)  d_in[3];
    const float* covalent_radii = (const float*)d_in[4];
    float* out = (float*)d_out;

    int n_edges = in_sizes[0];            // E
    int n_nodes = in_sizes[1] / N_ELEMS;  // N

    {
        int cover = n_nodes > out_size ? n_nodes : out_size;
        int pairs = (cover + 1) / 2;
        int blocks = (pairs + NP_NT - 1) / NP_NT;
        node_prep_kernel<<<blocks, NP_NT>>>(node_attrs, out, n_nodes, out_size);
    }

    int smem_bytes = NPAIR * 8 * (int)sizeof(float4) + PACKED_N;  // ~63KB
    cudaFuncSetAttribute(edge_kernel,
                         cudaFuncAttributeMaxDynamicSharedMemorySize,
                         smem_bytes);
    edge_kernel<<<EDGE_GRID, NT, smem_bytes>>>(x, edge_index, atomic_numbers,
                                               covalent_radii, out,
                                               n_edges, n_nodes);
}

// round 17
// speedup vs baseline: 1.0015x; 1.0015x over previous
#include <cuda_runtime.h>
#include <cuda_bf16.h>

// ZBL basis: per-edge screened Coulomb repulsion with polynomial cutoff,
// scatter-summed into receiver nodes.
//
// Inputs (metadata order):
//   d_in[0]: x               float32 [E, 1]   (E = 3,200,000)
//   d_in[1]: node_attrs      float32 [N, 10]  (N = 100,000)
//   d_in[2]: edge_index      int32   [2, E]
//   d_in[3]: atomic_numbers  int32   [10]
//   d_in[4]: covalent_radii  float32 [119]
// Output: V_ZBL float32 [N]
//
// SINGLE fused kernel (eliminates the node_prep launch + its graph-node
// overhead, ~2.3us of harness total):
//  Phase A (per block): compute a slice of the nibble element table
//    (register-resident argmax, 2 nodes/thread), zero the output slice,
//    build the 8x-replicated float4 pair LUT in smem.
//  Grid barrier: software sense barrier. Grid = 296 = EXACTLY one
//    co-resident wave (2 blocks/SM, smem-limited) -> spin is deadlock-free.
//    Writers: threadfence + arrive; last block resets arrive counter and
//    bumps the monotonic release counter; waiters read release BEFORE
//    arriving (bump can only occur after all arrivals -> race-free).
//  Phase B: copy nibble table to smem; converged edge loop (software-
//    pipelined .cg streams, conflict-free LDS, predicated red.global.add).

#define MAX_NODES 100352            // >= N, even, multiple of 32
#define PACKED_N  (MAX_NODES / 2)   // nibble-packed element table bytes
#define N_ELEMS   10
#define NPAIR     (N_ELEMS * N_ELEMS)
#define NT        512
#define EDGE_GRID 296               // 2 blocks/SM x 148 SMs, one wave

__device__ unsigned char g_e4[PACKED_N];   // 2 nodes/byte: elem idx nibbles
__device__ unsigned int  g_arrive = 0;     // barrier arrive counter
__device__ unsigned int  g_release = 0;    // monotonic release counter

__device__ __forceinline__ float ex2f(float a) {
    float r; asm("ex2.approx.f32 %0, %1;" : "=f"(r) : "f"(a)); return r;
}
__device__ __forceinline__ float frcpf(float a) {
    float r; asm("rcp.approx.f32 %0, %1;" : "=f"(r) : "f"(a)); return r;
}

// Predicated no-return global float add; no memory clobber (write-only out).
__device__ __forceinline__ void red_add_if(float* addr, float val, float rr) {
    asm volatile(
        "{\n\t"
        ".reg .pred p;\n\t"
        "setp.lt.f32 p, %1, 0f3F800000;\n\t"   // rr < 1.0f
        "@p red.global.add.f32 [%0], %2;\n\t"
        "}"
        :: "l"(addr), "f"(rr), "f"(val));
}

__device__ __forceinline__ int argmax10(const float* v) {
    int best = 0;
    float bv = v[0];
#pragma unroll
    for (int j = 1; j < N_ELEMS; j++) {
        if (v[j] > bv) { bv = v[j]; best = j; }
    }
    return best;
}

// ---------------------------------------------------------------------------
// Edge math (unchanged, converged)
// ---------------------------------------------------------------------------
__device__ __forceinline__ void process_edge(
    int s, int r, float xi, int lane8,
    const unsigned char* __restrict__ s_e4,
    const float4* __restrict__ s_lut,   // [(eu*10+ev)*8 + (lane&7)]
    float* __restrict__ out)
{
    int eu = (s_e4[s >> 1] >> ((s & 1) << 2)) & 15;
    int ev = (s_e4[r >> 1] >> ((r & 1) << 2)) & 15;
    float4 p = s_lut[((eu * N_ELEMS + ev) << 3) + lane8];
    // p = (inv_rmax, invA, pref, 0)

    float rr = xi * p.x;
    float t  = xi * p.y;

    const float K0 = -3.2f    * 1.44269504f;
    const float K1 = -0.9423f * 1.44269504f;
    const float K2 = -0.4028f * 1.44269504f;
    const float K3 = -0.2016f * 1.44269504f;
    float phi = 0.1818f  * ex2f(K0 * t)
              + 0.5099f  * ex2f(K1 * t)
              + 0.2802f  * ex2f(K2 * t)
              + 0.02817f * ex2f(K3 * t);

    // polynomial envelope, p=6: 1 - 28 r^6 + 48 r^7 - 21 r^8
    float r2 = rr * rr;
    float r3 = r2 * rr;
    float r6 = r3 * r3;
    float env = fmaf(-28.0f, r6, 1.0f);
    env = fmaf(48.0f, r6 * rr, env);
    env = fmaf(-21.0f, r6 * r2, env);

    float val = p.z * phi * frcpf(xi) * env;
    red_add_if(out + r, val, rr);
}

// ---------------------------------------------------------------------------
// Fused kernel
// ---------------------------------------------------------------------------
__global__ void __launch_bounds__(NT, 2)
fused_kernel(const float* __restrict__ x,
             const int* __restrict__ ei,
             const float* __restrict__ attrs,
             const int* __restrict__ atomic_numbers,
             const float* __restrict__ radii_g,
             float* __restrict__ out,
             int n_edges, int n_nodes, int out_n) {
    extern __shared__ char smem[];
    float4* s_lut = (float4*)smem;                  // NPAIR*8 float4 = 12.8KB
    unsigned char* s_e4 = (unsigned char*)(s_lut + NPAIR * 8);

    int tid = threadIdx.x;
    int lane8 = tid & 7;

    // ---------------- Phase A: node table slice + output zeroing ----------
    {
        int cover = n_nodes > out_n ? n_nodes : out_n;
        int pairs = (cover + 1) >> 1;                       // 2 nodes/pair
        int ppb = (pairs + (int)gridDim.x - 1) / (int)gridDim.x;
        int p0 = blockIdx.x * ppb;
        int p1 = p0 + ppb; if (p1 > pairs) p1 = pairs;
        for (int pp = p0 + tid; pp < p1; pp += NT) {
            int n0 = 2 * pp;
            if (n0 < n_nodes) {
                float v[20];
                const float4* a4 =
                    (const float4*)(attrs + (size_t)n0 * N_ELEMS);
#pragma unroll
                for (int k = 0; k < 5; k++) {
                    float4 q = __ldcg(a4 + k);
                    v[4 * k + 0] = q.x; v[4 * k + 1] = q.y;
                    v[4 * k + 2] = q.z; v[4 * k + 3] = q.w;
                }
                unsigned char packed = (unsigned char)argmax10(v);
                if (n0 + 1 < n_nodes)
                    packed |= (unsigned char)(argmax10(v + N_ELEMS) << 4);
                g_e4[pp] = packed;
            }
            if (n0 < out_n)     out[n0] = 0.0f;
            if (n0 + 1 < out_n) out[n0 + 1] = 0.0f;
        }
    }

    // 8x-replicated float4 pair LUT (independent of node table)
    if (tid < NPAIR) {
        int i = tid / N_ELEMS, j = tid % N_ELEMS;
        int Zi = atomic_numbers[i], Zj = atomic_numbers[j];
        float Zif = (float)Zi, Zjf = (float)Zj;
        float irm = 1.0f / (radii_g[Zi] + radii_g[Zj]);
        float ia  = (powf(Zif, 0.3f) + powf(Zjf, 0.3f))
                    * (1.0f / (0.4543f * 0.529f));
        float pf  = 0.5f * 14.3996f * Zif * Zjf;
        float4 v = make_float4(irm, ia, pf, 0.0f);
        int b = tid << 3;
#pragma unroll
        for (int c = 0; c < 8; c++) s_lut[b + c] = v;
    }

    // ---------------- Grid barrier (one-wave grid: deadlock-free) ---------
    __syncthreads();                       // all phase-A stores issued
    if (tid == 0) {
        unsigned int gen = *(volatile unsigned int*)&g_release;
        __threadfence();                   // publish g_e4 + out zeroes
        unsigned int prev = atomicAdd(&g_arrive, 1u);
        if (prev == gridDim.x - 1u) {
            atomicExch(&g_arrive, 0u);     // reset for next graph replay
            __threadfence();
            atomicAdd(&g_release, 1u);     // release everyone
        } else {
            while (*(volatile unsigned int*)&g_release == gen) { }
        }
        __threadfence();                   // acquire side
    }
    __syncthreads();

    // ---------------- Phase B: copy table to smem, edge loop --------------
    {
        const uint4* ge = (const uint4*)g_e4;
        uint4* se = (uint4*)s_e4;
        int nvec = (((n_nodes + 1) >> 1) + 15) >> 4;
        for (int w = tid; w < nvec; w += NT) se[w] = __ldcg(ge + w);
    }
    __syncthreads();

    const int4*   si = (const int4*)ei;
    const int4*   ri = (const int4*)(ei + n_edges);
    const float4* x4 = (const float4*)x;
    int n4 = n_edges >> 2;

    // Block-balanced contiguous chunk; threads stride NT within it.
    int q   = n4 / gridDim.x;
    int rem = n4 - q * gridDim.x;
    int b   = blockIdx.x;
    int start = b * q + (b < rem ? b : rem);
    int end   = start + q + (b < rem ? 1 : 0);

    int g = start + tid;
    // Software pipeline: prefetch next iteration's streams (.cg, read-once).
    int4 ss, rr; float4 xx;
    bool act = g < end;
    if (act) { ss = __ldcg(si + g); rr = __ldcg(ri + g); xx = __ldcg(x4 + g); }

    while (act) {
        int gn = g + NT;
        bool actn = gn < end;
        int4 ssn, rrn; float4 xxn;
        if (actn) {
            ssn = __ldcg(si + gn); rrn = __ldcg(ri + gn); xxn = __ldcg(x4 + gn);
        }

        process_edge(ss.x, rr.x, xx.x, lane8, s_e4, s_lut, out);
        process_edge(ss.y, rr.y, xx.y, lane8, s_e4, s_lut, out);
        process_edge(ss.z, rr.z, xx.z, lane8, s_e4, s_lut, out);
        process_edge(ss.w, rr.w, xx.w, lane8, s_e4, s_lut, out);

        ss = ssn; rr = rrn; xx = xxn;
        g = gn; act = actn;
    }

    // scalar tail (n_edges not divisible by 4)
    for (int i = (n4 << 2) + blockIdx.x * NT + tid; i < n_edges;
         i += gridDim.x * NT) {
        process_edge(__ldcg(ei + i), __ldcg(ei + n_edges + i), __ldcg(x + i),
                     lane8, s_e4, s_lut, out);
    }
}

extern "C" void kernel_launch(void* const* d_in, const int* in_sizes, int n_in,
                              void* d_out, int out_size) {
    const float* x              = (const float*)d_in[0];
    const float* node_attrs     = (const float*)d_in[1];
    const int*   edge_index     = (const int*)  d_in[2];
    const int*   atomic_numbers = (const int*)  d_in[3];
    const float* covalent_radii = (const float*)d_in[4];
    float* out = (float*)d_out;

    int n_edges = in_sizes[0];            // E
    int n_nodes = in_sizes[1] / N_ELEMS;  // N

    int smem_bytes = NPAIR * 8 * (int)sizeof(float4) + PACKED_N;  // ~63KB
    cudaFuncSetAttribute(fused_kernel,
                         cudaFuncAttributeMaxDynamicSharedMemorySize,
                         smem_bytes);
    // ONE kernel, ONE exact wave (2 blocks/SM x 148 SMs)
    fused_kernel<<<EDGE_GRID, NT, smem_bytes>>>(x, edge_index, node_attrs,
                                                atomic_numbers, covalent_radii,
                                                out, n_edges, n_nodes,
                                                out_size);
}